// round 2
// baseline (speedup 1.0000x reference)
#include <cuda_runtime.h>

// Problem constants
#define B_  64
#define H_  128
#define W_  128
#define R_  4
#define GW_ 32
#define N_  1024   // GH*GW
#define D_  16
#define S_  32

#define BSPLIT 4                 // b-loop split factor
#define BCHUNK (B_ / BSPLIT)     // 16 batches per warp

// Fused kernel:
//   out[b,n,d,s] = sum_r x[b, (n/32)*4+r, (n%32)*4+r] * pesos[n,d,s,r,r]
// One warp handles (n, 4 consecutive d, 16 b's).
// Lane = (d_off = lane>>3, s-quad = (lane&7)*4). Weights live in registers
// for the whole b-loop (16x reuse); pesos re-read by the other 3 b-chunks
// hits L2 (32 MiB < 126 MB L2).
__global__ void __launch_bounds__(256) conexao_fused_kernel(
    const float* __restrict__ x, const float* __restrict__ pesos,
    float* __restrict__ out) {

    int gwarp = (blockIdx.x * blockDim.x + threadIdx.x) >> 5;  // 0..16383
    int lane  = threadIdx.x & 31;

    int bg   = gwarp & (BSPLIT - 1);          // which b-chunk
    int warp = gwarp >> 2;                    // 0..4095 = N*D/4
    int n  = warp >> 2;                       // 0..1023
    int d  = ((warp & 3) << 2) + (lane >> 3); // 0..15
    int s4 = (lane & 7) << 2;                 // s base of this lane's quad

    // 16 diagonal weights: pesos[((n*D+d)*S + s)*16 + r*5]
    const float* wbase = pesos + ((size_t)(n * D_ + d) * S_ + s4) * (R_ * R_);
    float w[4][4];
    #pragma unroll
    for (int ss = 0; ss < 4; ss++)
        #pragma unroll
        for (int r = 0; r < 4; r++)
            w[ss][r] = wbase[ss * (R_ * R_) + r * (R_ + 1)];

    // x patch-diagonal base for this n (lane-uniform -> broadcast loads)
    int i = n >> 5;                // grid row
    int j = n & (GW_ - 1);         // grid col
    const float* xb = x + i * (R_ * W_) + j * R_ + (size_t)(bg * BCHUNK) * (H_ * W_);

    float4* o = reinterpret_cast<float4*>(out)
              + ((size_t)(n * D_ + d) * S_ + s4) / 4
              + (size_t)(bg * BCHUNK) * ((N_ * D_ * S_) / 4);
    const int o_stride = (N_ * D_ * S_) / 4;

    #pragma unroll 4
    for (int bi = 0; bi < BCHUNK; bi++) {
        const float* xp = xb + (size_t)bi * (H_ * W_);
        float x0 = __ldg(xp + 0 * W_ + 0);
        float x1 = __ldg(xp + 1 * W_ + 1);
        float x2 = __ldg(xp + 2 * W_ + 2);
        float x3 = __ldg(xp + 3 * W_ + 3);
        float4 ov;
        ov.x = x0 * w[0][0] + x1 * w[0][1] + x2 * w[0][2] + x3 * w[0][3];
        ov.y = x0 * w[1][0] + x1 * w[1][1] + x2 * w[1][2] + x3 * w[1][3];
        ov.z = x0 * w[2][0] + x1 * w[2][1] + x2 * w[2][2] + x3 * w[2][3];
        ov.w = x0 * w[3][0] + x1 * w[3][1] + x2 * w[3][2] + x3 * w[3][3];
        o[(size_t)bi * o_stride] = ov;        // warp stores 2KB contiguous
    }
}

extern "C" void kernel_launch(void* const* d_in, const int* in_sizes, int n_in,
                              void* d_out, int out_size) {
    const float* x     = (const float*)d_in[0];   // [64,1,128,128]
    const float* pesos = (const float*)d_in[1];   // [1024,16,32,4,4]
    float* out = (float*)d_out;                   // [64,1024,16,32]

    // N*D/4 * BSPLIT warps = 16384 warps = 2048 blocks of 256
    conexao_fused_kernel<<<(N_ * D_ / 4) * BSPLIT * 32 / 256, 256>>>(x, pesos, out);
}

// round 3
// speedup vs baseline: 1.5086x; 1.5086x over previous
#include <cuda_runtime.h>

// Problem constants
#define B_  64
#define H_  128
#define W_  128
#define R_  4
#define GW_ 32
#define N_  1024   // GH*GW
#define D_  16
#define S_  32

// One block per n. 256 threads.
//   thread t: warp w = t>>5, lane l = t&31
//   q  = (w>>1)*32 + l   in [0,128)  -> (d = q>>3, s4 = (q&7)*4)
//   bh = w&1             -> batches [bh*32, bh*32+32)
// Warp covers 32 consecutive s-quads -> each STG.128 is a 2KB contiguous
// warp store. All global loads happen in the prologue; the b-loop touches
// only smem (broadcast LDS) + registers.
__global__ void __launch_bounds__(256) conexao_block_kernel(
    const float* __restrict__ x, const float* __restrict__ pesos,
    float* __restrict__ out) {

    const int n = blockIdx.x;          // 0..1023
    const int t = threadIdx.x;
    const int w = t >> 5;
    const int l = t & 31;
    const int q  = ((w >> 1) << 5) + l;    // 0..127  (d, s-quad)
    const int bh = w & 1;                  // batch half
    const int d  = q >> 3;
    const int s4 = (q & 7) << 2;

    __shared__ float4 xds[B_];         // patch diagonals for all 64 b (1 KiB)

    // Prologue A: extract x diagonals (threads 0..63, one b each)
    if (t < B_) {
        const int i = n >> 5;
        const int j = n & (GW_ - 1);
        const float* xp = x + (size_t)t * (H_ * W_) + i * (R_ * W_) + j * R_;
        float4 v;
        v.x = __ldg(xp + 0 * W_ + 0);
        v.y = __ldg(xp + 1 * W_ + 1);
        v.z = __ldg(xp + 2 * W_ + 2);
        v.w = __ldg(xp + 3 * W_ + 3);
        xds[t] = v;
    }

    // Prologue B: 16 diagonal weights for this thread's (d, s-quad)
    const float* wbase = pesos + ((size_t)(n * D_ + d) * S_ + s4) * (R_ * R_);
    float wr[4][4];
    #pragma unroll
    for (int ss = 0; ss < 4; ss++)
        #pragma unroll
        for (int r = 0; r < 4; r++)
            wr[ss][r] = __ldg(wbase + ss * (R_ * R_) + r * (R_ + 1));

    __syncthreads();

    // Main loop: 32 batches, all-register/smem compute + streaming stores
    const int b0 = bh * 32;
    float4* o = reinterpret_cast<float4*>(out)
              + ((size_t)b0 * N_ + n) * (D_ * S_ / 4) + q;
    const size_t o_stride = (size_t)N_ * (D_ * S_ / 4);   // per-b stride in float4

    #pragma unroll 8
    for (int bi = 0; bi < 32; bi++) {
        float4 xv = xds[b0 + bi];      // warp-uniform -> LDS broadcast
        float4 ov;
        ov.x = xv.x * wr[0][0] + xv.y * wr[0][1] + xv.z * wr[0][2] + xv.w * wr[0][3];
        ov.y = xv.x * wr[1][0] + xv.y * wr[1][1] + xv.z * wr[1][2] + xv.w * wr[1][3];
        ov.z = xv.x * wr[2][0] + xv.y * wr[2][1] + xv.z * wr[2][2] + xv.w * wr[2][3];
        ov.w = xv.x * wr[3][0] + xv.y * wr[3][1] + xv.z * wr[3][2] + xv.w * wr[3][3];
        o[(size_t)bi * o_stride] = ov;
    }
}

extern "C" void kernel_launch(void* const* d_in, const int* in_sizes, int n_in,
                              void* d_out, int out_size) {
    const float* x     = (const float*)d_in[0];   // [64,1,128,128]
    const float* pesos = (const float*)d_in[1];   // [1024,16,32,4,4]
    float* out = (float*)d_out;                   // [64,1024,16,32]

    conexao_block_kernel<<<N_, 256>>>(x, pesos, out);
}

// round 4
// speedup vs baseline: 1.6872x; 1.1184x over previous
#include <cuda_runtime.h>

// Problem constants
#define B_  64
#define H_  128
#define W_  128
#define R_  4
#define GW_ 32
#define N_  1024   // GH*GW
#define D_  16
#define S_  32

// One block per n. 256 threads.
//   thread t: warp w = t>>5, lane l = t&31
//   q  = (w>>1)*32 + l   in [0,128)  -> (d = q>>3, s4 = (q&7)*4)
//   bh = w&1             -> batches [bh*32, bh*32+32)
// Warp covers 32 consecutive s-quads -> each STG.128 is a 2KB contiguous
// warp store. All global loads happen in the prologue; the b-loop touches
// only smem (broadcast LDS) + registers. Output stores use evict-first so
// pesos/x stay L2-resident across graph replays.
__global__ void __launch_bounds__(256) conexao_block_kernel(
    const float* __restrict__ x, const float* __restrict__ pesos,
    float* __restrict__ out) {

    const int n = blockIdx.x;          // 0..1023
    const int t = threadIdx.x;
    const int w = t >> 5;
    const int l = t & 31;
    const int q  = ((w >> 1) << 5) + l;    // 0..127  (d, s-quad)
    const int bh = w & 1;                  // batch half
    const int d  = q >> 3;
    const int s4 = (q & 7) << 2;

    __shared__ float xds[B_ * R_];     // patch diagonals for all 64 b (1 KiB)

    // Prologue B issued first: 16 diagonal weights for this thread's (d, s-quad)
    const float* wbase = pesos + ((size_t)(n * D_ + d) * S_ + s4) * (R_ * R_);
    float wr[4][4];
    #pragma unroll
    for (int ss = 0; ss < 4; ss++)
        #pragma unroll
        for (int r = 0; r < 4; r++)
            wr[ss][r] = __ldg(wbase + ss * (R_ * R_) + r * (R_ + 1));

    // Prologue A: extract x diagonals, one scalar load per thread (256 = B*R)
    {
        const int b = t >> 2;          // 0..63
        const int r = t & 3;           // 0..3
        const int i = n >> 5;
        const int j = n & (GW_ - 1);
        xds[t] = __ldg(x + (size_t)b * (H_ * W_)
                         + (i * R_ + r) * W_ + (j * R_ + r));
    }

    __syncthreads();

    // Main loop: 32 batches, register/smem compute + evict-first streaming stores
    const int b0 = bh * 32;
    const float4* xdv = reinterpret_cast<const float4*>(xds);
    float4* o = reinterpret_cast<float4*>(out)
              + ((size_t)b0 * N_ + n) * (D_ * S_ / 4) + q;
    const size_t o_stride = (size_t)N_ * (D_ * S_ / 4);   // per-b stride in float4

    #pragma unroll 8
    for (int bi = 0; bi < 32; bi++) {
        float4 xv = xdv[b0 + bi];      // warp-uniform -> LDS broadcast
        float4 ov;
        ov.x = xv.x * wr[0][0] + xv.y * wr[0][1] + xv.z * wr[0][2] + xv.w * wr[0][3];
        ov.y = xv.x * wr[1][0] + xv.y * wr[1][1] + xv.z * wr[1][2] + xv.w * wr[1][3];
        ov.z = xv.x * wr[2][0] + xv.y * wr[2][1] + xv.z * wr[2][2] + xv.w * wr[2][3];
        ov.w = xv.x * wr[3][0] + xv.y * wr[3][1] + xv.z * wr[3][2] + xv.w * wr[3][3];
        __stcs(&o[(size_t)bi * o_stride], ov);   // st.global.cs: evict-first in L2
    }
}

extern "C" void kernel_launch(void* const* d_in, const int* in_sizes, int n_in,
                              void* d_out, int out_size) {
    const float* x     = (const float*)d_in[0];   // [64,1,128,128]
    const float* pesos = (const float*)d_in[1];   // [1024,16,32,4,4]
    float* out = (float*)d_out;                   // [64,1024,16,32]

    conexao_block_kernel<<<N_, 256>>>(x, pesos, out);
}

// round 5
// speedup vs baseline: 1.9456x; 1.1532x over previous
#include <cuda_runtime.h>

// Problem constants
#define B_  64
#define H_  128
#define W_  128
#define R_  4
#define GW_ 32
#define N_  1024   // GH*GW
#define D_  16
#define S_  32

#define QROW 17    // padded row stride (floats) for diag smem -> conflict-free

// One block per n, 256 threads.
// Thread t: warp w=t>>5, lane l=t&31; q = (w>>1)*32+l in [0,128) -> (d=q>>3,
// s4=(q&7)*4); bh = w&1 -> batches [bh*32, bh*32+32).
//
// Pesos diagonal is extracted COOPERATIVELY: thread t loads element m=t&15 of
// 64-float rows (t>>4)+16k  (4 L1 lines per warp-op instead of 32), staged in
// padded smem, then each thread picks up its own 16 weights conflict-free.
// b-loop: LDS-broadcast xd + 16 FMA + evict-first STG.128 (2KB/warp).
__global__ void __launch_bounds__(256) conexao_block_kernel(
    const float* __restrict__ x, const float* __restrict__ pesos,
    float* __restrict__ out) {

    const int n = blockIdx.x;          // 0..1023
    const int t = threadIdx.x;
    const int w = t >> 5;
    const int l = t & 31;
    const int q  = ((w >> 1) << 5) + l;    // 0..127  (d, s-quad)
    const int bh = w & 1;                  // batch half

    __shared__ float diagp[128 * QROW];    // 2176 floats (~8.5 KB)
    __shared__ float xds[B_ * R_];         // 1 KiB

    // Phase 1: cooperative pesos-diagonal extraction (coalesced-ish LDG)
    {
        const float* pn = pesos + (size_t)n * (D_ * S_ * R_ * R_);
        const int m    = t & 15;                        // diag idx in row
        const int P    = ((m >> 2) << 4) + 5 * (m & 3); // offset of diag elem
        const int row0 = t >> 4;                        // 0..15
        #pragma unroll
        for (int k = 0; k < 8; k++) {
            const int row = row0 + 16 * k;              // 0..127 (= quad q')
            diagp[row * QROW + m] = __ldg(pn + row * 64 + P);
        }
    }

    // Phase 1b: x patch-diagonals, one scalar load per thread (256 = B*R)
    {
        const int b = t >> 2;          // 0..63
        const int r = t & 3;           // 0..3
        const int i = n >> 5;
        const int j = n & (GW_ - 1);
        xds[t] = __ldg(x + (size_t)b * (H_ * W_)
                         + (i * R_ + r) * W_ + (j * R_ + r));
    }

    __syncthreads();

    // Phase 2: this thread's 16 diagonal weights (conflict-free LDS: stride 17)
    float wr[4][4];
    #pragma unroll
    for (int ss = 0; ss < 4; ss++)
        #pragma unroll
        for (int r = 0; r < 4; r++)
            wr[ss][r] = diagp[q * QROW + ss * 4 + r];

    // Main loop: 32 batches, smem/register compute + evict-first streaming stores
    const int b0 = bh * 32;
    const float4* xdv = reinterpret_cast<const float4*>(xds);
    float4* o = reinterpret_cast<float4*>(out)
              + ((size_t)b0 * N_ + n) * (D_ * S_ / 4) + q;
    const size_t o_stride = (size_t)N_ * (D_ * S_ / 4);   // per-b stride (float4)

    #pragma unroll 8
    for (int bi = 0; bi < 32; bi++) {
        float4 xv = xdv[b0 + bi];      // warp-uniform -> LDS broadcast
        float4 ov;
        ov.x = xv.x * wr[0][0] + xv.y * wr[0][1] + xv.z * wr[0][2] + xv.w * wr[0][3];
        ov.y = xv.x * wr[1][0] + xv.y * wr[1][1] + xv.z * wr[1][2] + xv.w * wr[1][3];
        ov.z = xv.x * wr[2][0] + xv.y * wr[2][1] + xv.z * wr[2][2] + xv.w * wr[2][3];
        ov.w = xv.x * wr[3][0] + xv.y * wr[3][1] + xv.z * wr[3][2] + xv.w * wr[3][3];
        __stcs(&o[(size_t)bi * o_stride], ov);   // st.global.cs: evict-first
    }
}

extern "C" void kernel_launch(void* const* d_in, const int* in_sizes, int n_in,
                              void* d_out, int out_size) {
    const float* x     = (const float*)d_in[0];   // [64,1,128,128]
    const float* pesos = (const float*)d_in[1];   // [1024,16,32,4,4]
    float* out = (float*)d_out;                   // [64,1024,16,32]

    conexao_block_kernel<<<N_, 256>>>(x, pesos, out);
}